// round 16
// baseline (speedup 1.0000x reference)
#include <cuda_runtime.h>
#include <cstddef>
#include <cstdint>

#define DIM    1024
#define HEADS  16
#define DEPTH  64
#define BATCH  4
#define SEQ    2048
#define ROWS   (BATCH * SEQ)   // 8192

#define PGRID   304            // persistent grid for flash (128-thr CTAs)
#define PGRIDW  152            // persistent grid for wide GEMM (256-thr CTAs)

// ---------------- scratch (device globals; no allocation allowed) ----------
__device__ float g_rq [(size_t)ROWS * DIM];   // rna-rounded q
__device__ float g_rkc[(size_t)ROWS * DIM];   // gathered+rounded compact k rows
__device__ float g_rvc[(size_t)ROWS * DIM];   // gathered+rounded compact v rows
__device__ float g_WQt[(size_t)DIM * DIM];    // transposed + rounded [n][k]
__device__ float g_WKt[(size_t)DIM * DIM];
__device__ float g_WVt[(size_t)DIM * DIM];
__device__ float g_WOt[(size_t)DIM * DIM];
__device__ float g_Qh [(size_t)BATCH * HEADS * SEQ * DEPTH]; // [B,H,S,D]
__device__ float g_Kc [(size_t)BATCH * HEADS * SEQ * DEPTH]; // compact [B,H,i,D]
__device__ float g_Vc [(size_t)BATCH * HEADS * SEQ * DEPTH]; // compact [B,H,i,D]
__device__ float g_VcT[(size_t)BATCH * HEADS * DEPTH * SEQ]; // compact V^T [d][i]
__device__ float g_Att[(size_t)ROWS * DIM];                  // [B,S,DIM] rounded
__device__ int   g_cnt[BATCH];                 // padded count (mult of 128)
__device__ int   g_idx[BATCH * SEQ];           // compact slot -> original key
__device__ float g_bias[BATCH * SEQ];          // additive bias per compact slot

// ---------------- helpers ---------------------------------------------------
__device__ __forceinline__ unsigned f2tf(float x) {
    unsigned u;
    asm("cvt.rna.tf32.f32 %0, %1;" : "=r"(u) : "f"(x));
    return u;
}
__device__ __forceinline__ float tf(float x) { return __uint_as_float(f2tf(x)); }
__device__ __forceinline__ float4 tf4(float4 v) {
    return make_float4(tf(v.x), tf(v.y), tf(v.z), tf(v.w));
}
__device__ __forceinline__ uint32_t smem_u32(const void* p) {
    uint32_t a;
    asm("{ .reg .u64 t; cvta.to.shared.u64 t, %1; cvt.u32.u64 %0, t; }"
        : "=r"(a) : "l"(p));
    return a;
}
__device__ __forceinline__ void cp16(void* dst, const void* src) {
    unsigned d = (unsigned)__cvta_generic_to_shared(dst);
    asm volatile("cp.async.cg.shared.global [%0], [%1], 16;" :: "r"(d), "l"(src));
}
#define CP_COMMIT() asm volatile("cp.async.commit_group;")

// D += A(16x8) * B(8x8), tf32, row.col
__device__ __forceinline__ void mma8(float* d, const unsigned* a, const unsigned* b) {
    asm volatile(
        "mma.sync.aligned.m16n8k8.row.col.f32.tf32.tf32.f32 "
        "{%0,%1,%2,%3},{%4,%5,%6,%7},{%8,%9},{%0,%1,%2,%3};"
        : "+f"(d[0]), "+f"(d[1]), "+f"(d[2]), "+f"(d[3])
        : "r"(a[0]), "r"(a[1]), "r"(a[2]), "r"(a[3]), "r"(b[0]), "r"(b[1]));
}
__device__ __forceinline__ void ldsm4(unsigned* r, uint32_t saddr) {
    asm volatile("ldmatrix.sync.aligned.m8n8.x4.shared.b16 {%0,%1,%2,%3}, [%4];"
        : "=r"(r[0]), "=r"(r[1]), "=r"(r[2]), "=r"(r[3]) : "r"(saddr));
}

// ---------------------------------------------------------------------------
// Prepass: rna-round q only
// ---------------------------------------------------------------------------
__global__ void __launch_bounds__(256) round_q(
    const float* __restrict__ q, float* __restrict__ rq)
{
    size_t i = ((size_t)blockIdx.x * 256 + threadIdx.x) * 4;
    *(float4*)(rq + i) = tf4(*(const float4*)(q + i));
}

// Weight transpose + rounding: Wt[n][k] = tf(W[k][n])
__global__ void __launch_bounds__(256) transpose_w(
    const float* __restrict__ WQ, const float* __restrict__ WK,
    const float* __restrict__ WV, const float* __restrict__ WO,
    float* __restrict__ WQt, float* __restrict__ WKt,
    float* __restrict__ WVt, float* __restrict__ WOt)
{
    __shared__ float t[32][33];
    const float* W;
    float* Wt;
    switch (blockIdx.z) {
        case 0: W = WQ; Wt = WQt; break;
        case 1: W = WK; Wt = WKt; break;
        case 2: W = WV; Wt = WVt; break;
        default: W = WO; Wt = WOt; break;
    }
    int tx = threadIdx.x & 31, ty = threadIdx.x >> 5;
    int bx = blockIdx.x << 5, by = blockIdx.y << 5;
#pragma unroll
    for (int j = 0; j < 32; j += 8)
        t[ty + j][tx] = W[(size_t)(by + ty + j) * DIM + bx + tx];
    __syncthreads();
#pragma unroll
    for (int j = 0; j < 32; j += 8)
        Wt[(size_t)(bx + ty + j) * DIM + by + tx] = tf(t[tx][ty + j]);
}

// ---------------------------------------------------------------------------
// Compaction (R12-proven)
// ---------------------------------------------------------------------------
__global__ void __launch_bounds__(256) build_compact(
    const float* __restrict__ mask, int* __restrict__ cnt,
    int* __restrict__ idx, float* __restrict__ bias)
{
    __shared__ int cs[256];
    const int b = blockIdx.x, t = threadIdx.x;
    const float* m = mask + (size_t)b * SEQ;

    int local[8], lc = 0;
#pragma unroll
    for (int j = 0; j < 8; j++) {
        int s = t * 8 + j;
        if (m[s] == 0.f) local[lc++] = s;
    }
    cs[t] = lc;
    __syncthreads();
    for (int d = 1; d < 256; d <<= 1) {
        int v = (t >= d) ? cs[t - d] : 0;
        __syncthreads();
        cs[t] += v;
        __syncthreads();
    }
    const int off = cs[t] - lc;
    const int total = cs[255];

    if (total == 0) {
#pragma unroll
        for (int j = 0; j < 8; j++) {
            int s = t * 8 + j;
            idx[b * SEQ + s] = s;
            bias[b * SEQ + s] = m[s] * 1e9f;
        }
        if (t == 0) cnt[b] = SEQ;
        return;
    }

    for (int j = 0; j < lc; j++) {
        idx[b * SEQ + off + j] = local[j];
        bias[b * SEQ + off + j] = 0.f;
    }
    const int padded = ((total + 127) >> 7) << 7;
    for (int s = total + t; s < padded; s += 256) {
        idx[b * SEQ + s] = 0;
        bias[b * SEQ + s] = 1e9f;
    }
    if (t == 0) cnt[b] = padded;
}

// Gather + round compact input rows
__global__ void __launch_bounds__(256) gather_round_kv(
    const float* __restrict__ k, const float* __restrict__ v,
    const int* __restrict__ idx, const int* __restrict__ cnt,
    float* __restrict__ rkc, float* __restrict__ rvc)
{
    const int b = blockIdx.y;
    const int i = blockIdx.x;
    if (i >= cnt[b]) return;
    const int src = idx[b * SEQ + i];
    const float* S = (blockIdx.z ? v : k) + ((size_t)b * SEQ + src) * DIM;
    float* D = (blockIdx.z ? rvc : rkc) + ((size_t)b * SEQ + i) * DIM;
    int c = threadIdx.x << 2;
    *(float4*)(D + c) = tf4(*(const float4*)(S + c));
}

// Per-head transpose of compact V
__global__ void __launch_bounds__(256) transpose_vc(
    const float* __restrict__ Vc, const int* __restrict__ cnt,
    float* __restrict__ VcT)
{
    __shared__ float t[32][33];
    const int bh = blockIdx.z, b = bh >> 4;
    const int tx = threadIdx.x & 31, ty = threadIdx.x >> 5;
    const int s0 = blockIdx.x << 5, d0 = blockIdx.y << 5;
    if (s0 >= cnt[b]) return;
    const float* src = Vc + (size_t)bh * SEQ * DEPTH;
    float* dst = VcT + (size_t)bh * DEPTH * SEQ;
#pragma unroll
    for (int j = 0; j < 32; j += 8)
        t[ty + j][tx] = src[(size_t)(s0 + ty + j) * DEPTH + d0 + tx];
    __syncthreads();
#pragma unroll
    for (int j = 0; j < 32; j += 8)
        dst[(size_t)(d0 + ty + j) * SEQ + s0 + tx] = t[tx][ty + j];
}

// ---------------------------------------------------------------------------
// WIDE TF32 GEMM tile body: one 128x256 C tile, K=1024, 256 thr = 8 warps
// (2x4), warp tile 64x64. 3-stage/2-deep single-sync cp.async pipeline,
// 48KB stages (A 16KB + B 32KB), SW128 swizzle, ldmatrix fragments.
// MODE 0: flat. MODE 1: scatter rows to [B,H,S,D]. MODE 2: compact scatter.
// ---------------------------------------------------------------------------
#define GSTW 49152
#define GEMM_SMEM (3 * GSTW)

template <int MODE>
__device__ __forceinline__ void gemm_body(
    const float* __restrict__ A, const float* __restrict__ Bt,
    float* __restrict__ C, int m0, int n0, int bsel)
{
    extern __shared__ char gsm[];

    const int tid = threadIdx.x, lane = tid & 31, w = tid >> 5;
    const int g = lane >> 2, tg = lane & 3;
    const int wm = (w & 1) << 6;       // 0,64
    const int wn = (w >> 1) << 6;      // 0,64,128,192

    const int arow = (lane & 7) + ((lane >> 3) & 1) * 8;
    const int achk = (lane >> 4);
    const int brow = (lane & 7) + (lane >> 4) * 8;
    const int bchk = ((lane >> 3) & 1);

    const int cr = tid >> 3;           // 0..31
    const int cc = tid & 7;

    float acc[2][8][4];
#pragma unroll
    for (int i = 0; i < 2; i++)
#pragma unroll
        for (int j = 0; j < 8; j++)
#pragma unroll
            for (int c = 0; c < 4; c++) acc[i][j][c] = 0.f;
    float acc2[2][8][4];
#pragma unroll
    for (int i = 0; i < 2; i++)
#pragma unroll
        for (int j = 0; j < 8; j++)
#pragma unroll
            for (int c = 0; c < 4; c++) acc2[i][j][c] = 0.f;

    auto stage_copy = [&](int s, int p) {
        char* st = gsm + p * GSTW;
        const float* Ag = A  + (size_t)m0 * DIM + s * 32;
        const float* Bg = Bt + (size_t)n0 * DIM + s * 32;
#pragma unroll
        for (int t = 0; t < 4; t++) {   // A: 128 rows
            int r = cr + t * 32;
            uint32_t off = r * 128 + ((cc ^ (r & 7)) << 4);
            cp16(st + off, Ag + (size_t)r * DIM + (cc << 2));
        }
#pragma unroll
        for (int t = 0; t < 8; t++) {   // B: 256 rows
            int r = cr + t * 32;
            uint32_t off = r * 128 + ((cc ^ (r & 7)) << 4);
            cp16(st + 16384 + off, Bg + (size_t)r * DIM + (cc << 2));
        }
        CP_COMMIT();
    };

    __syncthreads();        // tile boundary: buffers free of previous tile
    stage_copy(0, 0);
    stage_copy(1, 1);

    const int NS = DIM / 32;   // 32
    for (int s = 0; s < NS; s++) {
        asm volatile("cp.async.wait_group 1;" ::: "memory");
        __syncthreads();    // stage s visible; buffer (s+2)%3 free

        if (s + 2 < NS) stage_copy(s + 2, (s + 2) % 3);
        else            CP_COMMIT();

        const uint32_t sA = smem_u32(gsm + (s % 3) * GSTW);
        const uint32_t sB = sA + 16384;

#pragma unroll
        for (int k0 = 0; k0 < 4; k0++) {
            unsigned af[4][4];
#pragma unroll
            for (int mf = 0; mf < 4; mf++) {
                int r = wm + (mf << 4) + arow;
                int ch = (k0 << 1) + achk;
                ldsm4(af[mf], sA + r * 128 + ((ch ^ (r & 7)) << 4));
            }
            unsigned bf[8][2];
#pragma unroll
            for (int nfp = 0; nfp < 4; nfp++) {
                int r = wn + (nfp << 4) + brow;
                int ch = (k0 << 1) + bchk;
                unsigned t[4];
                ldsm4(t, sB + r * 128 + ((ch ^ (r & 7)) << 4));
                bf[2 * nfp][0] = t[0];     bf[2 * nfp][1] = t[1];
                bf[2 * nfp + 1][0] = t[2]; bf[2 * nfp + 1][1] = t[3];
            }
#pragma unroll
            for (int nf = 0; nf < 8; nf++) {
#pragma unroll
                for (int mf = 0; mf < 2; mf++) {
                    mma8(acc[mf][nf],  af[mf],     bf[nf]);
                    mma8(acc2[mf][nf], af[mf + 2], bf[nf]);
                }
            }
        }
    }

    // epilogue (acc: mf 0-1, acc2: mf 2-3)
#pragma unroll
    for (int mfq = 0; mfq < 4; mfq++) {
        const float (*ac)[4] = (mfq < 2) ? acc[mfq] : acc2[mfq - 2];
        int r0 = m0 + wm + (mfq << 4) + g;
#pragma unroll
        for (int nf = 0; nf < 8; nf++) {
            int c = n0 + wn + (nf << 3) + (tg << 1);
            if (MODE == 0) {
                *(float2*)&C[(size_t)r0 * DIM + c] =
                    make_float2(ac[nf][0], ac[nf][1]);
                *(float2*)&C[(size_t)(r0 + 8) * DIM + c] =
                    make_float2(ac[nf][2], ac[nf][3]);
            } else if (MODE == 1) {
                int h = c >> 6, d = c & 63;
                int bb0 = r0 >> 11, s0 = r0 & 2047;
                int bb1 = (r0 + 8) >> 11, s1 = (r0 + 8) & 2047;
                size_t i0 = (((size_t)(bb0 * HEADS + h) * SEQ + s0) << 6) + d;
                size_t i1 = (((size_t)(bb1 * HEADS + h) * SEQ + s1) << 6) + d;
                *(float2*)&C[i0] = make_float2(tf(ac[nf][0]), tf(ac[nf][1]));
                *(float2*)&C[i1] = make_float2(tf(ac[nf][2]), tf(ac[nf][3]));
            } else {
                int h = c >> 6, d = c & 63;
                size_t i0 = (((size_t)(bsel * HEADS + h) * SEQ + r0) << 6) + d;
                size_t i1 = (((size_t)(bsel * HEADS + h) * SEQ + r0 + 8) << 6) + d;
                *(float2*)&C[i0] = make_float2(tf(ac[nf][0]), tf(ac[nf][1]));
                *(float2*)&C[i1] = make_float2(tf(ac[nf][2]), tf(ac[nf][3]));
            }
        }
    }
}

// persistent QKV projection over dynamic tile list (128x256 tiles)
__global__ void __launch_bounds__(256, 1) gemm_qkvc(
    const float* __restrict__ rq, const float* __restrict__ rkc,
    const float* __restrict__ rvc,
    const float* __restrict__ WQt, const float* __restrict__ WKt,
    const float* __restrict__ WVt,
    float* __restrict__ Qh, float* __restrict__ Kc, float* __restrict__ Vc,
    const int* __restrict__ cnt)
{
    int kt[4];
#pragma unroll
    for (int b = 0; b < 4; b++) kt[b] = cnt[b] >> 7;
    const int ktot = kt[0] + kt[1] + kt[2] + kt[3];
    const int total = 256 + 8 * ktot;   // Q: 64m x 4n; K/V: 2 x 4n x ktot

    for (int t = blockIdx.x; t < total; t += gridDim.x) {
        if (t < 256) {
            gemm_body<1>(rq, WQt, Qh, (t >> 2) << 7, (t & 3) << 8, 0);
        } else {
            int u = t - 256;
            int proj = u / (4 * ktot);
            u -= proj * 4 * ktot;
            int mt = u >> 2, nt = u & 3;
            int b = 0, m = mt;
#pragma unroll
            for (int bb = 0; bb < 3; bb++)
                if (m >= kt[b]) { m -= kt[b]; b++; }
            const float* A = (proj ? rvc : rkc) + (size_t)b * SEQ * DIM;
            const float* B = proj ? WVt : WKt;
            float* C = proj ? Vc : Kc;
            gemm_body<2>(A, B, C, m << 7, nt << 8, b);
        }
    }
}

// persistent output projection: 256 tiles (64m x 4n)
__global__ void __launch_bounds__(256, 1) gemm_out(
    const float* __restrict__ A, const float* __restrict__ Bt,
    float* __restrict__ C)
{
    for (int t = blockIdx.x; t < 256; t += gridDim.x)
        gemm_body<0>(A, Bt, C, (t >> 2) << 7, (t & 3) << 8, 0);
}

// ---------------------------------------------------------------------------
// Flash attention over COMPACTED keys, persistent (R13-proven, 2 barriers/kt).
// ---------------------------------------------------------------------------
#define FST 68
#define FA_SMEM_FLOATS (384 * FST + 64)
#define FA_SMEM_BYTES  (FA_SMEM_FLOATS * 4)
#define NQT (SEQ / 128)          // 16 q-tiles per (b,h)

__global__ void __launch_bounds__(128, 2) flash_tf32(
    const float* __restrict__ Qh, const float* __restrict__ Kc,
    const float* __restrict__ VcT, const float* __restrict__ Bias,
    const int* __restrict__ Cnt, float* __restrict__ Att)
{
    extern __shared__ float smf[];
    float* Qs  = smf;                    // [q][d] 128x68
    float* Ks  = smf + 128 * FST;        // [j][d] 64x68
    float* Vt  = smf + 192 * FST;        // [d][j] 64x68
    float* Ps  = smf + 256 * FST;        // [q][j] 128x68
    float* Msh = smf + 384 * FST;        // [64]

    const int tid = threadIdx.x, lane = tid & 31, w = tid >> 5;
    const int g = lane >> 2, tg = lane & 3;
    const int q0 = w << 5;               // 0,32,64,96

    const int arow  = (lane & 7) + ((lane >> 3) & 1) * 8;
    const int akoff = (lane >> 4) * 4;
    const int brow  = (lane & 7) + (lane >> 4) * 8;
    const int bkoff = ((lane >> 3) & 1) * 4;

    const uint32_t sQs = smem_u32(Qs);
    const uint32_t sKs = smem_u32(Ks);
    const uint32_t sVt = smem_u32(Vt);
    const uint32_t sPs = smem_u32(Ps);

    for (int tile = blockIdx.x; tile < BATCH * HEADS * NQT; tile += gridDim.x) {
        const int qt = tile % NQT;
        const int bh = tile / NQT;       // b*HEADS + h
        const int h  = bh % HEADS;
        const int b  = bh / HEADS;
        const int nkt = Cnt[b] >> 6;     // compact key tiles

        const float* Qg = Qh  + ((size_t)bh * SEQ + qt * 128) * DEPTH;
        const float* Kg = Kc  + (size_t)bh * SEQ * DEPTH;
        const float* Vg = VcT + (size_t)bh * DEPTH * SEQ;  // [d][i]
        const float* Mg = Bias + (size_t)b * SEQ;

        __syncthreads();   // protect Qs from prev tile's in-flight QK reads

        // Q tile: pre-rounded tf32; x0.125 exact (power of two)
#pragma unroll
        for (int it = 0; it < 16; it++) {
            int idx = tid + it * 128;
            int r = idx >> 4, c = (idx & 15) << 2;
            float4 qv = *(const float4*)(Qg + r * DEPTH + c);
            *(float4*)&Qs[r * FST + c] = make_float4(
                0.125f * qv.x, 0.125f * qv.y, 0.125f * qv.z, 0.125f * qv.w);
        }

        float o[2][8][4];
#pragma unroll
        for (int mf = 0; mf < 2; mf++)
#pragma unroll
            for (int nf = 0; nf < 8; nf++)
#pragma unroll
                for (int c = 0; c < 4; c++) o[mf][nf][c] = 0.f;
        float mrow[4] = {-1e30f, -1e30f, -1e30f, -1e30f};
        float lrow[4] = {0.f, 0.f, 0.f, 0.f};

        for (int kt = 0; kt < nkt; kt++) {
            __syncthreads();             // (A) prev Ps/Vt reads done
            const float* Kgt = Kg + kt * 64 * DEPTH;
            const float* Vgt = Vg + kt * 64;       // column offset in [d][i]
#pragma unroll
            for (int it = 0; it < 8; it++) {
                int idx = tid + it * 128;
                int r = idx >> 4, c = (idx & 15) << 2;
                cp16(&Ks[r * FST + c], Kgt + r * DEPTH + c);
                cp16(&Vt[r * FST + c], Vgt + (size_t)r * SEQ + c);
            }
            CP_COMMIT();
            if (tid < 64) Msh[tid] = Mg[kt * 64 + tid];
            asm volatile("cp.async.wait_group 0;" ::: "memory");
            __syncthreads();             // (B) tiles visible

            // S = Q @ K^T
            float s[2][8][4];
#pragma unroll
            for (int mf = 0; mf < 2; mf++)
#pragma unroll
                for (int nf = 0; nf < 8; nf++)
#pragma unroll
                    for (int c = 0; c < 4; c++) s[mf][nf][c] = 0.f;

#pragma unroll
            for (int k0 = 0; k0 < 8; k0++) {
                unsigned qa[2][4];
                ldsm4(qa[0], sQs + 4u * ((q0 + arow) * FST + (k0 << 3) + akoff));
                ldsm4(qa[1], sQs + 4u * ((q0 + 16 + arow) * FST + (k0 << 3) + akoff));
                unsigned bf[8][2];
#pragma unroll
                for (int nfp = 0; nfp < 4; nfp++) {
                    unsigned t[4];
                    ldsm4(t, sKs + 4u * (((nfp << 4) + brow) * FST + (k0 << 3) + bkoff));
                    bf[2 * nfp][0] = t[0];     bf[2 * nfp][1] = t[1];
                    bf[2 * nfp + 1][0] = t[2]; bf[2 * nfp + 1][1] = t[3];
                }
#pragma unroll
                for (int nf = 0; nf < 8; nf++) {
                    mma8(s[0][nf], qa[0], bf[nf]);
                    mma8(s[1][nf], qa[1], bf[nf]);
                }
            }

            // bias + online softmax
            float mx[4] = {-1e30f, -1e30f, -1e30f, -1e30f};
#pragma unroll
            for (int mf = 0; mf < 2; mf++)
#pragma unroll
                for (int nf = 0; nf < 8; nf++) {
                    float k0v = Msh[(nf << 3) + (tg << 1)];
                    float k1v = Msh[(nf << 3) + (tg << 1) + 1];
                    s[mf][nf][0] -= k0v; s[mf][nf][1] -= k1v;
                    s[mf][nf][2] -= k0v; s[mf][nf][3] -= k1v;
                    mx[mf * 2 + 0] = fmaxf(mx[mf * 2 + 0], fmaxf(s[mf][nf][0], s[mf][nf][1]));
                    mx[mf * 2 + 1] = fmaxf(mx[mf * 2 + 1], fmaxf(s[mf][nf][2], s[mf][nf][3]));
                }
#pragma unroll
            for (int r = 0; r < 4; r++) {
                mx[r] = fmaxf(mx[r], __shfl_xor_sync(0xffffffffu, mx[r], 1));
                mx[r] = fmaxf(mx[r], __shfl_xor_sync(0xffffffffu, mx[r], 2));
            }
            float al[4];
#pragma unroll
            for (int r = 0; r < 4; r++) {
                float mn = fmaxf(mrow[r], mx[r]);
                al[r] = __expf(mrow[r] - mn);
                mrow[r] = mn;
            }
            float sm[4] = {0.f, 0.f, 0.f, 0.f};
#pragma unroll
            for (int mf = 0; mf < 2; mf++)
#pragma unroll
                for (int nf = 0; nf < 8; nf++) {
                    s[mf][nf][0] = __expf(s[mf][nf][0] - mrow[mf * 2 + 0]);
                    s[mf][nf][1] = __expf(s[mf][nf][1] - mrow[mf * 2 + 0]);
                    s[mf][nf][2] = __expf(s[mf][nf][2] - mrow[mf * 2 + 1]);
                    s[mf][nf][3] = __expf(s[mf][nf][3] - mrow[mf * 2 + 1]);
                    sm[mf * 2 + 0] += s[mf][nf][0] + s[mf][nf][1];
                    sm[mf * 2 + 1] += s[mf][nf][2] + s[mf][nf][3];
                }
#pragma unroll
            for (int r = 0; r < 4; r++) {
                sm[r] += __shfl_xor_sync(0xffffffffu, sm[r], 1);
                sm[r] += __shfl_xor_sync(0xffffffffu, sm[r], 2);
                lrow[r] = lrow[r] * al[r] + sm[r];
            }
#pragma unroll
            for (int mf = 0; mf < 2; mf++)
#pragma unroll
                for (int nf = 0; nf < 8; nf++) {
                    o[mf][nf][0] *= al[mf * 2 + 0]; o[mf][nf][1] *= al[mf * 2 + 0];
                    o[mf][nf][2] *= al[mf * 2 + 1]; o[mf][nf][3] *= al[mf * 2 + 1];
                }

            // P -> smem: warp-private rows
#pragma unroll
            for (int mf = 0; mf < 2; mf++) {
                int m = q0 + (mf << 4);
#pragma unroll
                for (int nf = 0; nf < 8; nf++) {
                    *(float2*)&Ps[(m + g) * FST + (nf << 3) + (tg << 1)] =
                        make_float2(s[mf][nf][0], s[mf][nf][1]);
                    *(float2*)&Ps[(m + g + 8) * FST + (nf << 3) + (tg << 1)] =
                        make_float2(s[mf][nf][2], s[mf][nf][3]);
                }
            }
            __syncwarp();

            // O += P @ V
#pragma unroll
            for (int j0 = 0; j0 < 8; j0++) {
                unsigned pa[2][4];
                ldsm4(pa[0], sPs + 4u * ((q0 + arow) * FST + (j0 << 3) + akoff));
                ldsm4(pa[1], sPs + 4u * ((q0 + 16 + arow) * FST + (j0 << 3) + akoff));
                unsigned bf[8][2];
#pragma unroll
                for (int nfp = 0; nfp < 4; nfp++) {
                    unsigned t[4];
                    ldsm4(t, sVt + 4u * (((nfp << 4) + brow) * FST + (j0 << 3) + bkoff));
                    bf[2 * nfp][0] = t[0];     bf[2 * nfp][1] = t[1];
                    bf[2 * nfp + 1][0] = t[2]; bf[2 * nfp + 1][1] = t[3];
                }
#pragma unroll
                for (int nf = 0; nf < 8; nf++) {
                    mma8(o[0][nf], pa[0], bf[nf]);
                    mma8(o[1][nf], pa[1], bf[nf]);
                }
            }
        }

        // normalize + write tf32-rounded [B,S,DIM]
#pragma unroll
        for (int mf = 0; mf < 2; mf++) {
            float inv0 = 1.0f / lrow[mf * 2 + 0];
            float inv1 = 1.0f / lrow[mf * 2 + 1];
            int r0 = qt * 128 + q0 + (mf << 4) + g;
            int r1 = r0 + 8;
#pragma unroll
            for (int nf = 0; nf < 8; nf++) {
                int c = h * 64 + (nf << 3) + (tg << 1);
                *(float2*)&Att[(size_t)(b * SEQ + r0) * DIM + c] =
                    make_float2(tf(o[mf][nf][0] * inv0), tf(o[mf][nf][1] * inv0));
                *(float2*)&Att[(size_t)(b * SEQ + r1) * DIM + c] =
                    make_float2(tf(o[mf][nf][2] * inv1), tf(o[mf][nf][3] * inv1));
            }
        }
    }
}

// ---------------------------------------------------------------------------
extern "C" void kernel_launch(void* const* d_in, const int* in_sizes, int n_in,
                              void* d_out, int out_size)
{
    const float* q    = (const float*)d_in[0];
    const float* k    = (const float*)d_in[1];
    const float* v    = (const float*)d_in[2];
    const float* mask = (const float*)d_in[3];
    const float* WQ   = (const float*)d_in[4];
    const float* WK   = (const float*)d_in[5];
    const float* WV   = (const float*)d_in[6];
    const float* WO   = (const float*)d_in[7];
    float* out = (float*)d_out;

    float *rq, *rkc, *rvc, *WQt, *WKt, *WVt, *WOt, *Qh, *Kc, *Vc, *VcT, *Att, *bias;
    int *cnt, *idx;
    cudaGetSymbolAddress((void**)&rq,  g_rq);
    cudaGetSymbolAddress((void**)&rkc, g_rkc);
    cudaGetSymbolAddress((void**)&rvc, g_rvc);
    cudaGetSymbolAddress((void**)&WQt, g_WQt);
    cudaGetSymbolAddress((void**)&WKt, g_WKt);
    cudaGetSymbolAddress((void**)&WVt, g_WVt);
    cudaGetSymbolAddress((void**)&WOt, g_WOt);
    cudaGetSymbolAddress((void**)&Qh,  g_Qh);
    cudaGetSymbolAddress((void**)&Kc,  g_Kc);
    cudaGetSymbolAddress((void**)&Vc,  g_Vc);
    cudaGetSymbolAddress((void**)&VcT, g_VcT);
    cudaGetSymbolAddress((void**)&Att, g_Att);
    cudaGetSymbolAddress((void**)&cnt, g_cnt);
    cudaGetSymbolAddress((void**)&idx, g_idx);
    cudaGetSymbolAddress((void**)&bias, g_bias);

    cudaFuncSetAttribute(gemm_qkvc,
                         cudaFuncAttributeMaxDynamicSharedMemorySize, GEMM_SMEM);
    cudaFuncSetAttribute(gemm_out,
                         cudaFuncAttributeMaxDynamicSharedMemorySize, GEMM_SMEM);
    cudaFuncSetAttribute(flash_tf32,
                         cudaFuncAttributeMaxDynamicSharedMemorySize, FA_SMEM_BYTES);

    round_q<<<ROWS * DIM / 1024, 256>>>(q, rq);
    transpose_w<<<dim3(32, 32, 4), 256>>>(WQ, WK, WV, WO, WQt, WKt, WVt, WOt);
    build_compact<<<BATCH, 256>>>(mask, cnt, idx, bias);
    gather_round_kv<<<dim3(SEQ, BATCH, 2), 256>>>(k, v, idx, cnt, rkc, rvc);

    gemm_qkvc<<<PGRIDW, 256, GEMM_SMEM>>>(rq, rkc, rvc, WQt, WKt, WVt,
                                          Qh, Kc, Vc, cnt);

    transpose_vc<<<dim3(SEQ / 32, DEPTH / 32, BATCH * HEADS), 256>>>(Vc, cnt, VcT);

    flash_tf32<<<PGRID, 128, FA_SMEM_BYTES>>>(Qh, Kc, VcT, bias, cnt, Att);

    gemm_out<<<PGRIDW, 256, GEMM_SMEM>>>(Att, WOt, out);
}

// round 17
// speedup vs baseline: 1.0470x; 1.0470x over previous
#include <cuda_runtime.h>
#include <cstddef>
#include <cstdint>

#define DIM    1024
#define HEADS  16
#define DEPTH  64
#define BATCH  4
#define SEQ    2048
#define ROWS   (BATCH * SEQ)   // 8192

#define PGRID  304             // persistent grid: ~2 CTAs/SM

// ---------------- scratch (device globals; no allocation allowed) ----------
__device__ float g_rq [(size_t)ROWS * DIM];   // rna-rounded q
__device__ float g_rkc[(size_t)ROWS * DIM];   // gathered+rounded compact k rows
__device__ float g_rvc[(size_t)ROWS * DIM];   // gathered+rounded compact v rows
__device__ float g_WQt[(size_t)DIM * DIM];    // transposed + rounded [n][k]
__device__ float g_WKt[(size_t)DIM * DIM];
__device__ float g_WVt[(size_t)DIM * DIM];
__device__ float g_WOt[(size_t)DIM * DIM];
__device__ float g_Qh [(size_t)BATCH * HEADS * SEQ * DEPTH]; // [B,H,S,D]
__device__ float g_Kc [(size_t)BATCH * HEADS * SEQ * DEPTH]; // compact [B,H,i,D]
__device__ float g_VcT[(size_t)BATCH * HEADS * DEPTH * SEQ]; // compact V^T [d][i]
__device__ float g_Att[(size_t)ROWS * DIM];                  // [B,S,DIM] rounded
__device__ int   g_cnt[BATCH];                 // padded count (mult of 128)
__device__ int   g_idx[BATCH * SEQ];           // compact slot -> original key
__device__ float g_bias[BATCH * SEQ];          // additive bias per compact slot

// ---------------- helpers ---------------------------------------------------
__device__ __forceinline__ unsigned f2tf(float x) {
    unsigned u;
    asm("cvt.rna.tf32.f32 %0, %1;" : "=r"(u) : "f"(x));
    return u;
}
__device__ __forceinline__ float tf(float x) { return __uint_as_float(f2tf(x)); }
__device__ __forceinline__ float4 tf4(float4 v) {
    return make_float4(tf(v.x), tf(v.y), tf(v.z), tf(v.w));
}
__device__ __forceinline__ uint32_t smem_u32(const void* p) {
    uint32_t a;
    asm("{ .reg .u64 t; cvta.to.shared.u64 t, %1; cvt.u32.u64 %0, t; }"
        : "=r"(a) : "l"(p));
    return a;
}
__device__ __forceinline__ void cp16(void* dst, const void* src) {
    unsigned d = (unsigned)__cvta_generic_to_shared(dst);
    asm volatile("cp.async.cg.shared.global [%0], [%1], 16;" :: "r"(d), "l"(src));
}
#define CP_COMMIT() asm volatile("cp.async.commit_group;")

// D += A(16x8) * B(8x8), tf32, row.col
__device__ __forceinline__ void mma8(float* d, const unsigned* a, const unsigned* b) {
    asm volatile(
        "mma.sync.aligned.m16n8k8.row.col.f32.tf32.tf32.f32 "
        "{%0,%1,%2,%3},{%4,%5,%6,%7},{%8,%9},{%0,%1,%2,%3};"
        : "+f"(d[0]), "+f"(d[1]), "+f"(d[2]), "+f"(d[3])
        : "r"(a[0]), "r"(a[1]), "r"(a[2]), "r"(a[3]), "r"(b[0]), "r"(b[1]));
}
__device__ __forceinline__ void ldsm4(unsigned* r, uint32_t saddr) {
    asm volatile("ldmatrix.sync.aligned.m8n8.x4.shared.b16 {%0,%1,%2,%3}, [%4];"
        : "=r"(r[0]), "=r"(r[1]), "=r"(r[2]), "=r"(r[3]) : "r"(saddr));
}

// ---------------------------------------------------------------------------
// Prepass: rna-round q only
// ---------------------------------------------------------------------------
__global__ void __launch_bounds__(256) round_q(
    const float* __restrict__ q, float* __restrict__ rq)
{
    size_t i = ((size_t)blockIdx.x * 256 + threadIdx.x) * 4;
    *(float4*)(rq + i) = tf4(*(const float4*)(q + i));
}

// Weight transpose + rounding: Wt[n][k] = tf(W[k][n])
__global__ void __launch_bounds__(256) transpose_w(
    const float* __restrict__ WQ, const float* __restrict__ WK,
    const float* __restrict__ WV, const float* __restrict__ WO,
    float* __restrict__ WQt, float* __restrict__ WKt,
    float* __restrict__ WVt, float* __restrict__ WOt)
{
    __shared__ float t[32][33];
    const float* W;
    float* Wt;
    switch (blockIdx.z) {
        case 0: W = WQ; Wt = WQt; break;
        case 1: W = WK; Wt = WKt; break;
        case 2: W = WV; Wt = WVt; break;
        default: W = WO; Wt = WOt; break;
    }
    int tx = threadIdx.x & 31, ty = threadIdx.x >> 5;
    int bx = blockIdx.x << 5, by = blockIdx.y << 5;
#pragma unroll
    for (int j = 0; j < 32; j += 8)
        t[ty + j][tx] = W[(size_t)(by + ty + j) * DIM + bx + tx];
    __syncthreads();
#pragma unroll
    for (int j = 0; j < 32; j += 8)
        Wt[(size_t)(bx + ty + j) * DIM + by + tx] = tf(t[tx][ty + j]);
}

// ---------------------------------------------------------------------------
// Compaction (R12-proven): deterministic prefix scan, pad to mult of 128,
// pad slots bias=+1e9 (exp underflows to exact 0). Degenerate all-masked
// batch: identity + bias = mask*1e9.
// ---------------------------------------------------------------------------
__global__ void __launch_bounds__(256) build_compact(
    const float* __restrict__ mask, int* __restrict__ cnt,
    int* __restrict__ idx, float* __restrict__ bias)
{
    __shared__ int cs[256];
    const int b = blockIdx.x, t = threadIdx.x;
    const float* m = mask + (size_t)b * SEQ;

    int local[8], lc = 0;
#pragma unroll
    for (int j = 0; j < 8; j++) {
        int s = t * 8 + j;
        if (m[s] == 0.f) local[lc++] = s;
    }
    cs[t] = lc;
    __syncthreads();
    for (int d = 1; d < 256; d <<= 1) {
        int v = (t >= d) ? cs[t - d] : 0;
        __syncthreads();
        cs[t] += v;
        __syncthreads();
    }
    const int off = cs[t] - lc;
    const int total = cs[255];

    if (total == 0) {
#pragma unroll
        for (int j = 0; j < 8; j++) {
            int s = t * 8 + j;
            idx[b * SEQ + s] = s;
            bias[b * SEQ + s] = m[s] * 1e9f;
        }
        if (t == 0) cnt[b] = SEQ;
        return;
    }

    for (int j = 0; j < lc; j++) {
        idx[b * SEQ + off + j] = local[j];
        bias[b * SEQ + off + j] = 0.f;
    }
    const int padded = ((total + 127) >> 7) << 7;
    for (int s = total + t; s < padded; s += 256) {
        idx[b * SEQ + s] = 0;
        bias[b * SEQ + s] = 1e9f;
    }
    if (t == 0) cnt[b] = padded;
}

// Gather + round compact input rows
__global__ void __launch_bounds__(256) gather_round_kv(
    const float* __restrict__ k, const float* __restrict__ v,
    const int* __restrict__ idx, const int* __restrict__ cnt,
    float* __restrict__ rkc, float* __restrict__ rvc)
{
    const int b = blockIdx.y;
    const int i = blockIdx.x;
    if (i >= cnt[b]) return;
    const int src = idx[b * SEQ + i];
    const float* S = (blockIdx.z ? v : k) + ((size_t)b * SEQ + src) * DIM;
    float* D = (blockIdx.z ? rvc : rkc) + ((size_t)b * SEQ + i) * DIM;
    int c = threadIdx.x << 2;
    *(float4*)(D + c) = tf4(*(const float4*)(S + c));
}

// ---------------------------------------------------------------------------
// TF32 GEMM tile body (R13-proven 3-stage pipeline): one 128x128 C tile.
// MODE 0: flat. MODE 1: scatter rows to [B,H,S,D] (Q).
// MODE 2: compact scatter to [bsel,H,i,D] (K).
// MODE 3: compact TRANSPOSED scatter to VcT[bsel,H,d,i] (V).
// ---------------------------------------------------------------------------
#define GST 32768
#define GEMM_SMEM (3 * GST)

template <int MODE>
__device__ __forceinline__ void gemm_body(
    const float* __restrict__ A, const float* __restrict__ Bt,
    float* __restrict__ C, int m0, int n0, int bsel)
{
    extern __shared__ char gsm[];

    const int tid = threadIdx.x, lane = tid & 31, w = tid >> 5;
    const int g = lane >> 2, tg = lane & 3;
    const int wm = (w & 1) << 6;
    const int wn = (w >> 1) << 6;

    const int arow = (lane & 7) + ((lane >> 3) & 1) * 8;
    const int achk = (lane >> 4);
    const int brow = (lane & 7) + (lane >> 4) * 8;
    const int bchk = ((lane >> 3) & 1);

    const int cr = tid >> 3;
    const int cc = tid & 7;

    float acc[4][8][4];
#pragma unroll
    for (int i = 0; i < 4; i++)
#pragma unroll
        for (int j = 0; j < 8; j++)
#pragma unroll
            for (int c = 0; c < 4; c++) acc[i][j][c] = 0.f;

    auto stage_copy = [&](int s, int p) {
        char* st = gsm + p * GST;
        const float* Ag = A  + (size_t)m0 * DIM + s * 32;
        const float* Bg = Bt + (size_t)n0 * DIM + s * 32;
#pragma unroll
        for (int t = 0; t < 8; t++) {
            int r = cr + t * 16;
            uint32_t off = r * 128 + ((cc ^ (r & 7)) << 4);
            cp16(st + off,         Ag + (size_t)r * DIM + (cc << 2));
            cp16(st + 16384 + off, Bg + (size_t)r * DIM + (cc << 2));
        }
        CP_COMMIT();
    };

    stage_copy(0, 0);
    stage_copy(1, 1);
    stage_copy(2, 2);

    const int NS = DIM / 32;   // 32
    for (int s = 0; s < NS; s++) {
        int p = s % 3;
        asm volatile("cp.async.wait_group 2;" ::: "memory");
        __syncthreads();

        const uint32_t sA = smem_u32(gsm + p * GST);
        const uint32_t sB = sA + 16384;

#pragma unroll
        for (int k0 = 0; k0 < 4; k0++) {
            unsigned af[4][4];
#pragma unroll
            for (int mf = 0; mf < 4; mf++) {
                int r = wm + (mf << 4) + arow;
                int ch = (k0 << 1) + achk;
                ldsm4(af[mf], sA + r * 128 + ((ch ^ (r & 7)) << 4));
            }
            unsigned bf[8][2];
#pragma unroll
            for (int nfp = 0; nfp < 4; nfp++) {
                int r = wn + (nfp << 4) + brow;
                int ch = (k0 << 1) + bchk;
                unsigned t[4];
                ldsm4(t, sB + r * 128 + ((ch ^ (r & 7)) << 4));
                bf[2 * nfp][0] = t[0];     bf[2 * nfp][1] = t[1];
                bf[2 * nfp + 1][0] = t[2]; bf[2 * nfp + 1][1] = t[3];
            }
#pragma unroll
            for (int nf = 0; nf < 8; nf++)
#pragma unroll
                for (int mf = 0; mf < 4; mf++)
                    mma8(acc[mf][nf], af[mf], bf[nf]);
        }
        __syncthreads();

        if (s + 3 < NS) stage_copy(s + 3, p);
        else            CP_COMMIT();
    }

#pragma unroll
    for (int mf = 0; mf < 4; mf++) {
        int r0 = m0 + wm + (mf << 4) + g;
#pragma unroll
        for (int nf = 0; nf < 8; nf++) {
            int c = n0 + wn + (nf << 3) + (tg << 1);
            if (MODE == 0) {
                *(float2*)&C[(size_t)r0 * DIM + c] =
                    make_float2(acc[mf][nf][0], acc[mf][nf][1]);
                *(float2*)&C[(size_t)(r0 + 8) * DIM + c] =
                    make_float2(acc[mf][nf][2], acc[mf][nf][3]);
            } else if (MODE == 1) {
                int h = c >> 6, d = c & 63;
                int bb0 = r0 >> 11, s0 = r0 & 2047;
                int bb1 = (r0 + 8) >> 11, s1 = (r0 + 8) & 2047;
                size_t i0 = (((size_t)(bb0 * HEADS + h) * SEQ + s0) << 6) + d;
                size_t i1 = (((size_t)(bb1 * HEADS + h) * SEQ + s1) << 6) + d;
                *(float2*)&C[i0] = make_float2(tf(acc[mf][nf][0]), tf(acc[mf][nf][1]));
                *(float2*)&C[i1] = make_float2(tf(acc[mf][nf][2]), tf(acc[mf][nf][3]));
            } else if (MODE == 2) {
                int h = c >> 6, d = c & 63;   // r0 is batch-local compact row
                size_t i0 = (((size_t)(bsel * HEADS + h) * SEQ + r0) << 6) + d;
                size_t i1 = (((size_t)(bsel * HEADS + h) * SEQ + r0 + 8) << 6) + d;
                *(float2*)&C[i0] = make_float2(tf(acc[mf][nf][0]), tf(acc[mf][nf][1]));
                *(float2*)&C[i1] = make_float2(tf(acc[mf][nf][2]), tf(acc[mf][nf][3]));
            } else {
                // V^T: VcT[bh][d][i], i = compact row r0; c even => d, d+1
                int h = c >> 6, d = c & 63;
                float* p0 = C + ((size_t)(bsel * HEADS + h) * DEPTH + d) * SEQ;
                float* p1 = p0 + SEQ;   // d+1 (same head: d <= 62 since c even)
                p0[r0]     = tf(acc[mf][nf][0]);
                p1[r0]     = tf(acc[mf][nf][1]);
                p0[r0 + 8] = tf(acc[mf][nf][2]);
                p1[r0 + 8] = tf(acc[mf][nf][3]);
            }
        }
    }
}

// persistent QKV projection over dynamic tile list:
// Q: 512 tiles; K: 8n x ktot; V: 8n x ktot (writes VcT directly).
__global__ void __launch_bounds__(128, 2) gemm_qkvc(
    const float* __restrict__ rq, const float* __restrict__ rkc,
    const float* __restrict__ rvc,
    const float* __restrict__ WQt, const float* __restrict__ WKt,
    const float* __restrict__ WVt,
    float* __restrict__ Qh, float* __restrict__ Kc, float* __restrict__ VcT,
    const int* __restrict__ cnt)
{
    int kt[4];
#pragma unroll
    for (int b = 0; b < 4; b++) kt[b] = cnt[b] >> 7;
    const int ktot = kt[0] + kt[1] + kt[2] + kt[3];
    const int total = 512 + 16 * ktot;

    for (int t = blockIdx.x; t < total; t += gridDim.x) {
        if (t < 512) {
            gemm_body<1>(rq, WQt, Qh, (t >> 3) << 7, (t & 7) << 7, 0);
        } else {
            int u = t - 512;
            int proj = u / (8 * ktot);
            u -= proj * 8 * ktot;
            int mt = u >> 3, nt = u & 7;
            int b = 0, m = mt;
#pragma unroll
            for (int bb = 0; bb < 3; bb++)
                if (m >= kt[b]) { m -= kt[b]; b++; }
            if (proj == 0)
                gemm_body<2>(rkc + (size_t)b * SEQ * DIM, WKt, Kc,
                             m << 7, nt << 7, b);
            else
                gemm_body<3>(rvc + (size_t)b * SEQ * DIM, WVt, VcT,
                             m << 7, nt << 7, b);
        }
    }
}

// persistent output projection: 512 tiles
__global__ void __launch_bounds__(128, 2) gemm_out(
    const float* __restrict__ A, const float* __restrict__ Bt,
    float* __restrict__ C)
{
    for (int t = blockIdx.x; t < 512; t += gridDim.x)
        gemm_body<0>(A, Bt, C, (t >> 3) << 7, (t & 7) << 7, 0);
}

// ---------------------------------------------------------------------------
// Flash attention over COMPACTED keys, persistent (R13-proven, 2 barriers/kt).
// ---------------------------------------------------------------------------
#define FST 68
#define FA_SMEM_FLOATS (384 * FST + 64)
#define FA_SMEM_BYTES  (FA_SMEM_FLOATS * 4)
#define NQT (SEQ / 128)          // 16 q-tiles per (b,h)

__global__ void __launch_bounds__(128, 2) flash_tf32(
    const float* __restrict__ Qh, const float* __restrict__ Kc,
    const float* __restrict__ VcT, const float* __restrict__ Bias,
    const int* __restrict__ Cnt, float* __restrict__ Att)
{
    extern __shared__ float smf[];
    float* Qs  = smf;                    // [q][d] 128x68
    float* Ks  = smf + 128 * FST;        // [j][d] 64x68
    float* Vt  = smf + 192 * FST;        // [d][j] 64x68
    float* Ps  = smf + 256 * FST;        // [q][j] 128x68
    float* Msh = smf + 384 * FST;        // [64]

    const int tid = threadIdx.x, lane = tid & 31, w = tid >> 5;
    const int g = lane >> 2, tg = lane & 3;
    const int q0 = w << 5;               // 0,32,64,96

    const int arow  = (lane & 7) + ((lane >> 3) & 1) * 8;
    const int akoff = (lane >> 4) * 4;
    const int brow  = (lane & 7) + (lane >> 4) * 8;
    const int bkoff = ((lane >> 3) & 1) * 4;

    const uint32_t sQs = smem_u32(Qs);
    const uint32_t sKs = smem_u32(Ks);
    const uint32_t sVt = smem_u32(Vt);
    const uint32_t sPs = smem_u32(Ps);

    for (int tile = blockIdx.x; tile < BATCH * HEADS * NQT; tile += gridDim.x) {
        const int qt = tile % NQT;
        const int bh = tile / NQT;       // b*HEADS + h
        const int h  = bh % HEADS;
        const int b  = bh / HEADS;
        const int nkt = Cnt[b] >> 6;     // compact key tiles

        const float* Qg = Qh  + ((size_t)bh * SEQ + qt * 128) * DEPTH;
        const float* Kg = Kc  + (size_t)bh * SEQ * DEPTH;
        const float* Vg = VcT + (size_t)bh * DEPTH * SEQ;  // [d][i]
        const float* Mg = Bias + (size_t)b * SEQ;

        __syncthreads();   // protect Qs from prev tile's in-flight QK reads

        // Q tile: pre-rounded tf32; x0.125 exact (power of two)
#pragma unroll
        for (int it = 0; it < 16; it++) {
            int idx = tid + it * 128;
            int r = idx >> 4, c = (idx & 15) << 2;
            float4 qv = *(const float4*)(Qg + r * DEPTH + c);
            *(float4*)&Qs[r * FST + c] = make_float4(
                0.125f * qv.x, 0.125f * qv.y, 0.125f * qv.z, 0.125f * qv.w);
        }

        float o[2][8][4];
#pragma unroll
        for (int mf = 0; mf < 2; mf++)
#pragma unroll
            for (int nf = 0; nf < 8; nf++)
#pragma unroll
                for (int c = 0; c < 4; c++) o[mf][nf][c] = 0.f;
        float mrow[4] = {-1e30f, -1e30f, -1e30f, -1e30f};
        float lrow[4] = {0.f, 0.f, 0.f, 0.f};

        for (int kt = 0; kt < nkt; kt++) {
            __syncthreads();             // (A) prev Ps/Vt reads done
            const float* Kgt = Kg + kt * 64 * DEPTH;
            const float* Vgt = Vg + kt * 64;       // column offset in [d][i]
#pragma unroll
            for (int it = 0; it < 8; it++) {
                int idx = tid + it * 128;
                int r = idx >> 4, c = (idx & 15) << 2;
                cp16(&Ks[r * FST + c], Kgt + r * DEPTH + c);
                cp16(&Vt[r * FST + c], Vgt + (size_t)r * SEQ + c);
            }
            CP_COMMIT();
            if (tid < 64) Msh[tid] = Mg[kt * 64 + tid];
            asm volatile("cp.async.wait_group 0;" ::: "memory");
            __syncthreads();             // (B) tiles visible

            // S = Q @ K^T
            float s[2][8][4];
#pragma unroll
            for (int mf = 0; mf < 2; mf++)
#pragma unroll
                for (int nf = 0; nf < 8; nf++)
#pragma unroll
                    for (int c = 0; c < 4; c++) s[mf][nf][c] = 0.f;

#pragma unroll
            for (int k0 = 0; k0 < 8; k0++) {
                unsigned qa[2][4];
                ldsm4(qa[0], sQs + 4u * ((q0 + arow) * FST + (k0 << 3) + akoff));
                ldsm4(qa[1], sQs + 4u * ((q0 + 16 + arow) * FST + (k0 << 3) + akoff));
                unsigned bf[8][2];
#pragma unroll
                for (int nfp = 0; nfp < 4; nfp++) {
                    unsigned t[4];
                    ldsm4(t, sKs + 4u * (((nfp << 4) + brow) * FST + (k0 << 3) + bkoff));
                    bf[2 * nfp][0] = t[0];     bf[2 * nfp][1] = t[1];
                    bf[2 * nfp + 1][0] = t[2]; bf[2 * nfp + 1][1] = t[3];
                }
#pragma unroll
                for (int nf = 0; nf < 8; nf++) {
                    mma8(s[0][nf], qa[0], bf[nf]);
                    mma8(s[1][nf], qa[1], bf[nf]);
                }
            }

            // bias + online softmax
            float mx[4] = {-1e30f, -1e30f, -1e30f, -1e30f};
#pragma unroll
            for (int mf = 0; mf < 2; mf++)
#pragma unroll
                for (int nf = 0; nf < 8; nf++) {
                    float k0v = Msh[(nf << 3) + (tg << 1)];
                    float k1v = Msh[(nf << 3) + (tg << 1) + 1];
                    s[mf][nf][0] -= k0v; s[mf][nf][1] -= k1v;
                    s[mf][nf][2] -= k0v; s[mf][nf][3] -= k1v;
                    mx[mf * 2 + 0] = fmaxf(mx[mf * 2 + 0], fmaxf(s[mf][nf][0], s[mf][nf][1]));
                    mx[mf * 2 + 1] = fmaxf(mx[mf * 2 + 1], fmaxf(s[mf][nf][2], s[mf][nf][3]));
                }
#pragma unroll
            for (int r = 0; r < 4; r++) {
                mx[r] = fmaxf(mx[r], __shfl_xor_sync(0xffffffffu, mx[r], 1));
                mx[r] = fmaxf(mx[r], __shfl_xor_sync(0xffffffffu, mx[r], 2));
            }
            float al[4];
#pragma unroll
            for (int r = 0; r < 4; r++) {
                float mn = fmaxf(mrow[r], mx[r]);
                al[r] = __expf(mrow[r] - mn);
                mrow[r] = mn;
            }
            float sm[4] = {0.f, 0.f, 0.f, 0.f};
#pragma unroll
            for (int mf = 0; mf < 2; mf++)
#pragma unroll
                for (int nf = 0; nf < 8; nf++) {
                    s[mf][nf][0] = __expf(s[mf][nf][0] - mrow[mf * 2 + 0]);
                    s[mf][nf][1] = __expf(s[mf][nf][1] - mrow[mf * 2 + 0]);
                    s[mf][nf][2] = __expf(s[mf][nf][2] - mrow[mf * 2 + 1]);
                    s[mf][nf][3] = __expf(s[mf][nf][3] - mrow[mf * 2 + 1]);
                    sm[mf * 2 + 0] += s[mf][nf][0] + s[mf][nf][1];
                    sm[mf * 2 + 1] += s[mf][nf][2] + s[mf][nf][3];
                }
#pragma unroll
            for (int r = 0; r < 4; r++) {
                sm[r] += __shfl_xor_sync(0xffffffffu, sm[r], 1);
                sm[r] += __shfl_xor_sync(0xffffffffu, sm[r], 2);
                lrow[r] = lrow[r] * al[r] + sm[r];
            }
#pragma unroll
            for (int mf = 0; mf < 2; mf++)
#pragma unroll
                for (int nf = 0; nf < 8; nf++) {
                    o[mf][nf][0] *= al[mf * 2 + 0]; o[mf][nf][1] *= al[mf * 2 + 0];
                    o[mf][nf][2] *= al[mf * 2 + 1]; o[mf][nf][3] *= al[mf * 2 + 1];
                }

            // P -> smem: warp-private rows
#pragma unroll
            for (int mf = 0; mf < 2; mf++) {
                int m = q0 + (mf << 4);
#pragma unroll
                for (int nf = 0; nf < 8; nf++) {
                    *(float2*)&Ps[(m + g) * FST + (nf << 3) + (tg << 1)] =
                        make_float2(s[mf][nf][0], s[mf][nf][1]);
                    *(float2*)&Ps[(m + g + 8) * FST + (nf << 3) + (tg << 1)] =
                        make_float2(s[mf][nf][2], s[mf][nf][3]);
                }
            }
            __syncwarp();

            // O += P @ V
#pragma unroll
            for (int j0 = 0; j0 < 8; j0++) {
                unsigned pa[2][4];
                ldsm4(pa[0], sPs + 4u * ((q0 + arow) * FST + (j0 << 3) + akoff));
                ldsm4(pa[1], sPs + 4u * ((q0 + 16 + arow) * FST + (j0 << 3) + akoff));
                unsigned bf[8][2];
#pragma unroll
                for (int nfp = 0; nfp < 4; nfp++) {
                    unsigned t[4];
                    ldsm4(t, sVt + 4u * (((nfp << 4) + brow) * FST + (j0 << 3) + bkoff));
                    bf[2 * nfp][0] = t[0];     bf[2 * nfp][1] = t[1];
                    bf[2 * nfp + 1][0] = t[2]; bf[2 * nfp + 1][1] = t[3];
                }
#pragma unroll
                for (int nf = 0; nf < 8; nf++) {
                    mma8(o[0][nf], pa[0], bf[nf]);
                    mma8(o[1][nf], pa[1], bf[nf]);
                }
            }
        }

        // normalize + write tf32-rounded [B,S,DIM]
#pragma unroll
        for (int mf = 0; mf < 2; mf++) {
            float inv0 = 1.0f / lrow[mf * 2 + 0];
            float inv1 = 1.0f / lrow[mf * 2 + 1];
            int r0 = qt * 128 + q0 + (mf << 4) + g;
            int r1 = r0 + 8;
#pragma unroll
            for (int nf = 0; nf < 8; nf++) {
                int c = h * 64 + (nf << 3) + (tg << 1);
                *(float2*)&Att[(size_t)(b * SEQ + r0) * DIM + c] =
                    make_float2(tf(o[mf][nf][0] * inv0), tf(o[mf][nf][1] * inv0));
                *(float2*)&Att[(size_t)(b * SEQ + r1) * DIM + c] =
                    make_float2(tf(o[mf][nf][2] * inv1), tf(o[mf][nf][3] * inv1));
            }
        }
    }
}

// ---------------------------------------------------------------------------
extern "C" void kernel_launch(void* const* d_in, const int* in_sizes, int n_in,
                              void* d_out, int out_size)
{
    const float* q    = (const float*)d_in[0];
    const float* k    = (const float*)d_in[1];
    const float* v    = (const float*)d_in[2];
    const float* mask = (const float*)d_in[3];
    const float* WQ   = (const float*)d_in[4];
    const float* WK   = (const float*)d_in[5];
    const float* WV   = (const float*)d_in[6];
    const float* WO   = (const float*)d_in[7];
    float* out = (float*)d_out;

    float *rq, *rkc, *rvc, *WQt, *WKt, *WVt, *WOt, *Qh, *Kc, *VcT, *Att, *bias;
    int *cnt, *idx;
    cudaGetSymbolAddress((void**)&rq,  g_rq);
    cudaGetSymbolAddress((void**)&rkc, g_rkc);
    cudaGetSymbolAddress((void**)&rvc, g_rvc);
    cudaGetSymbolAddress((void**)&WQt, g_WQt);
    cudaGetSymbolAddress((void**)&WKt, g_WKt);
    cudaGetSymbolAddress((void**)&WVt, g_WVt);
    cudaGetSymbolAddress((void**)&WOt, g_WOt);
    cudaGetSymbolAddress((void**)&Qh,  g_Qh);
    cudaGetSymbolAddress((void**)&Kc,  g_Kc);
    cudaGetSymbolAddress((void**)&VcT, g_VcT);
    cudaGetSymbolAddress((void**)&Att, g_Att);
    cudaGetSymbolAddress((void**)&cnt, g_cnt);
    cudaGetSymbolAddress((void**)&idx, g_idx);
    cudaGetSymbolAddress((void**)&bias, g_bias);

    cudaFuncSetAttribute(gemm_qkvc,
                         cudaFuncAttributeMaxDynamicSharedMemorySize, GEMM_SMEM);
    cudaFuncSetAttribute(gemm_out,
                         cudaFuncAttributeMaxDynamicSharedMemorySize, GEMM_SMEM);
    cudaFuncSetAttribute(flash_tf32,
                         cudaFuncAttributeMaxDynamicSharedMemorySize, FA_SMEM_BYTES);

    round_q<<<ROWS * DIM / 1024, 256>>>(q, rq);
    transpose_w<<<dim3(32, 32, 4), 256>>>(WQ, WK, WV, WO, WQt, WKt, WVt, WOt);
    build_compact<<<BATCH, 256>>>(mask, cnt, idx, bias);
    gather_round_kv<<<dim3(SEQ, BATCH, 2), 256>>>(k, v, idx, cnt, rkc, rvc);

    gemm_qkvc<<<PGRID, 128, GEMM_SMEM>>>(rq, rkc, rvc, WQt, WKt, WVt,
                                         Qh, Kc, VcT, cnt);

    flash_tf32<<<PGRID, 128, FA_SMEM_BYTES>>>(Qh, Kc, VcT, bias, cnt, Att);

    gemm_out<<<PGRID, 128, GEMM_SMEM>>>(Att, WOt, out);
}